// round 10
// baseline (speedup 1.0000x reference)
#include <cuda_runtime.h>
#include <cuda_bf16.h>
#include <cstdint>
#include <math.h>

// ---------------- problem constants ----------------
#define BATCH    1024
#define TSTEPS   80
#define DIM      512
#define CLS      78
#define BLANK    77
#define PRED_LEN 30
#define ROWS     (BATCH * TSTEPS)     // 81920

#define ITEMS_PER_CTA 7
#define NCTAS    147                  // 146*7 + 2 = 1024 items
#define THREADS  384                  // 12 warps = 6 pairs
#define NKC      16                   // k32 chunks (512/32)

// ---------------- smem layout (bytes) ----------------
#define B_STRIDE  1088                // 1024 data + 64 pad (conflict-free LDS.128)
#define B_BYTES   (80 * B_STRIDE)     // 87040 each (hi, lo)
#define SM_BHI    0
#define SM_BLO    B_BYTES
#define SM_BIAS   (2 * B_BYTES)       // 174080 : 80 floats
#define SM_SBEST  (SM_BIAS + 320)     // 174400 : int sbest[560]
#define SM_MBOX   (SM_SBEST + 2240)   // 176640 : float4 mbox[6][2][32]
#define SM_UNIT   (SM_MBOX + 6144)    // 182784 : int unit[6]
#define SM_CTR    (SM_UNIT + 32)      // 182816
#define SM_TOTAL  (SM_CTR + 16)       // 182832

// B k-permutation matched to A fragments held as 4-consecutive-k float4s:
__device__ __forceinline__ int kperm(int k) {
    int grp = k >> 5, r = k & 31;
    int s = r >> 4;
    int t = (r & 15) >> 2;
    int idx = r & 3;
    return grp * 32 + t * 8 + s * 4 + idx;
}

__device__ __forceinline__ uint32_t pack_bf16(float a, float b) {
    uint32_t r;
    asm("cvt.rn.satfinite.bf16x2.f32 %0, %1, %2;" : "=r"(r) : "f"(b), "f"(a));
    return r;
}

__device__ __forceinline__ void split2(float a, float b, uint32_t& h, uint32_t& l) {
    h = pack_bf16(a, b);
    float ha = __uint_as_float(h << 16);
    float hb = __uint_as_float(h & 0xffff0000u);
    l = pack_bf16(a - ha, b - hb);
}

__device__ __forceinline__ void mma16816(float* c, uint32_t a0, uint32_t a1,
                                         uint32_t a2, uint32_t a3,
                                         uint32_t b0, uint32_t b1) {
    asm volatile(
        "mma.sync.aligned.m16n8k16.row.col.f32.bf16.bf16.f32 "
        "{%0,%1,%2,%3}, {%4,%5,%6,%7}, {%8,%9}, {%0,%1,%2,%3};"
        : "+f"(c[0]), "+f"(c[1]), "+f"(c[2]), "+f"(c[3])
        : "r"(a0), "r"(a1), "r"(a2), "r"(a3), "r"(b0), "r"(b1));
}

// ---------------------------------------------------------------------------
// Single kernel: paired-warp 32x40 GEMM tiles + softmax merge + CTC decode
// ---------------------------------------------------------------------------
__global__ void __launch_bounds__(THREADS, 1)
ctc_fused_kernel(const float* __restrict__ feat,
                 const float* __restrict__ Wg,
                 const float* __restrict__ bg,
                 float* __restrict__ out)
{
    extern __shared__ char sm[];
    const int tid  = threadIdx.x;
    const int lane = tid & 31;
    const int warp = tid >> 5;
    const int g    = lane >> 2;
    const int t    = lane & 3;
    const int p    = warp & 1;       // col half: cols [40p, 40p+40)
    const int pid  = warp >> 1;      // pair id 0..5
    const unsigned full = 0xffffffffu;

    const int it0      = blockIdx.x * ITEMS_PER_CTA;
    const int nitems   = min(ITEMS_PER_CTA, BATCH - it0);
    const int rows_cta = nitems * TSTEPS;
    const int nunits   = (rows_cta + 31) >> 5;
    int*    const sctr  = (int*)(sm + SM_CTR);
    int*    const sbest = (int*)(sm + SM_SBEST);
    int*    const upair = (int*)(sm + SM_UNIT) + pid;
    float4* const mbox  = (float4*)(sm + SM_MBOX) + pid * 64;   // [p][row32]

    if (tid == 0) *sctr = 0;

    // ---- build B = W^T bf16 hi/lo, k-permuted, zero-padded to 80 cols ----
    for (int idx = tid; idx < 80 * DIM; idx += THREADS) {
        int k = idx / 80;
        int n = idx - k * 80;
        float v = (n < CLS) ? Wg[k * CLS + n] : 0.0f;
        __nv_bfloat16 h = __float2bfloat16_rn(v);
        __nv_bfloat16 l = __float2bfloat16_rn(v - __bfloat162float(h));
        int byte = n * B_STRIDE + kperm(k) * 2;
        *(uint16_t*)(sm + SM_BHI + byte) = __bfloat16_as_ushort(h);
        *(uint16_t*)(sm + SM_BLO + byte) = __bfloat16_as_ushort(l);
    }
    if (tid < 80) ((float*)(sm + SM_BIAS))[tid] = (tid < CLS) ? bg[tid] : 0.0f;
    __syncthreads();
    const float* bias_sm = (const float*)(sm + SM_BIAS);

    for (;;) {
        if (p == 0 && lane == 0) *upair = atomicAdd(sctr, 1);
        asm volatile("bar.sync %0, %1;" :: "r"(pid + 1), "r"(64) : "memory");
        const int u = *upair;
        if (u >= nunits) break;

        const bool has2 = (rows_cta - 32 * u) >= 32;
        const size_t rb = (size_t)it0 * TSTEPS + (size_t)u * 32;

        // per-thread A base: row rb+g, float4 column t; rowpos rp -> +8*rp rows
        const float4* a4 = (const float4*)(feat + (rb + g) * DIM) + t;

        float c[2][5][4];
        #pragma unroll
        for (int rt = 0; rt < 2; rt++)
            #pragma unroll
            for (int j = 0; j < 5; j++)
                { c[rt][j][0]=0.f; c[rt][j][1]=0.f; c[rt][j][2]=0.f; c[rt][j][3]=0.f; }

        // register ring: Fb[slot][rp][s], prefetch distance 2
        float4 Fb[2][4][2];
        #pragma unroll
        for (int q = 0; q < 2; q++)
            #pragma unroll
            for (int rp = 0; rp < 4; rp++)
                #pragma unroll
                for (int s = 0; s < 2; s++)
                    Fb[q][rp][s] = a4[rp * 8 * (DIM/4) + q * 8 + s * 4];

        #pragma unroll 2
        for (int kc = 0; kc < NKC; kc++) {
            const int slot = kc & 1;

            uint32_t AH[4][2][2], AL[4][2][2];   // [rp][s][half]
            #pragma unroll
            for (int rp = 0; rp < 4; rp++)
                #pragma unroll
                for (int s = 0; s < 2; s++) {
                    split2(Fb[slot][rp][s].x, Fb[slot][rp][s].y, AH[rp][s][0], AL[rp][s][0]);
                    split2(Fb[slot][rp][s].z, Fb[slot][rp][s].w, AH[rp][s][1], AL[rp][s][1]);
                }

            if (kc + 2 < NKC) {
                #pragma unroll
                for (int rp = 0; rp < 4; rp++)
                    #pragma unroll
                    for (int s = 0; s < 2; s++)
                        Fb[slot][rp][s] = a4[rp * 8 * (DIM/4) + (kc + 2) * 8 + s * 4];
            }

            const int boff = kc * 64 + t * 16;
            #pragma unroll
            for (int j = 0; j < 5; j++) {
                const int n = 40 * p + 8 * j + g;
                uint4 bh = *(const uint4*)(sm + SM_BHI + n * B_STRIDE + boff);
                uint4 bl = *(const uint4*)(sm + SM_BLO + n * B_STRIDE + boff);
                float* c0 = c[0][j];
                float* c1 = c[1][j];
                // HH step0/1, rt-interleaved
                mma16816(c0, AH[0][0][0], AH[1][0][0], AH[0][0][1], AH[1][0][1], bh.x, bh.y);
                mma16816(c1, AH[2][0][0], AH[3][0][0], AH[2][0][1], AH[3][0][1], bh.x, bh.y);
                mma16816(c0, AH[0][1][0], AH[1][1][0], AH[0][1][1], AH[1][1][1], bh.z, bh.w);
                mma16816(c1, AH[2][1][0], AH[3][1][0], AH[2][1][1], AH[3][1][1], bh.z, bh.w);
                // HL
                mma16816(c0, AH[0][0][0], AH[1][0][0], AH[0][0][1], AH[1][0][1], bl.x, bl.y);
                mma16816(c1, AH[2][0][0], AH[3][0][0], AH[2][0][1], AH[3][0][1], bl.x, bl.y);
                mma16816(c0, AH[0][1][0], AH[1][1][0], AH[0][1][1], AH[1][1][1], bl.z, bl.w);
                mma16816(c1, AH[2][1][0], AH[3][1][0], AH[2][1][1], AH[3][1][1], bl.z, bl.w);
                // LH
                mma16816(c0, AL[0][0][0], AL[1][0][0], AL[0][0][1], AL[1][0][1], bh.x, bh.y);
                mma16816(c1, AL[2][0][0], AL[3][0][0], AL[2][0][1], AL[3][0][1], bh.x, bh.y);
                mma16816(c0, AL[0][1][0], AL[1][1][0], AL[0][1][1], AL[1][1][1], bh.z, bh.w);
                mma16816(c1, AL[2][1][0], AL[3][1][0], AL[2][1][1], AL[3][1][1], bh.z, bh.w);
            }
        }

        // ---- epilogue pass 1: per-half (max, sum, argmax) into mailbox ----
        float bbx[5], bby[5];
        #pragma unroll
        for (int j = 0; j < 5; j++) {
            float2 bv = *(const float2*)(bias_sm + 40 * p + 8 * j + 2 * t);
            bbx[j] = bv.x; bby[j] = bv.y;
        }
        #pragma unroll
        for (int rp = 0; rp < 4; rp++) {
            const int rt = rp >> 1, h = rp & 1;
            const bool valid = (rt == 0) || has2;
            float m = -INFINITY; int bi = 0;
            #pragma unroll
            for (int j = 0; j < 5; j++) {
                int col = 40 * p + 8 * j + 2 * t;
                float v0 = c[rt][j][2 * h]     + bbx[j];
                float v1 = c[rt][j][2 * h + 1] + bby[j];
                c[rt][j][2 * h]     = v0;
                c[rt][j][2 * h + 1] = v1;
                if (col     < CLS && v0 > m) { m = v0; bi = col; }
                if (col + 1 < CLS && v1 > m) { m = v1; bi = col + 1; }
            }
            #pragma unroll
            for (int d = 1; d <= 2; d <<= 1) {
                float om = __shfl_xor_sync(full, m, d);
                int   oi = __shfl_xor_sync(full, bi, d);
                if (om > m || (om == m && oi < bi)) { m = om; bi = oi; }
            }
            float s = 0.f;
            #pragma unroll
            for (int j = 0; j < 5; j++) {
                int col = 40 * p + 8 * j + 2 * t;
                float e0 = (col     < CLS) ? __expf(c[rt][j][2 * h]     - m) : 0.f;
                float e1 = (col + 1 < CLS) ? __expf(c[rt][j][2 * h + 1] - m) : 0.f;
                c[rt][j][2 * h]     = e0;
                c[rt][j][2 * h + 1] = e1;
                s += e0 + e1;
            }
            #pragma unroll
            for (int d = 1; d <= 2; d <<= 1)
                s += __shfl_xor_sync(full, s, d);
            if (t == 0 && valid)
                mbox[p * 32 + g + 8 * rp] = make_float4(m, s, __int_as_float(bi), 0.f);
        }
        asm volatile("bar.sync %0, %1;" :: "r"(pid + 1), "r"(64) : "memory");

        // ---- epilogue pass 2: merge halves, normalize, store ----
        #pragma unroll
        for (int rp = 0; rp < 4; rp++) {
            const int rt = rp >> 1, h = rp & 1;
            const bool valid = (rt == 0) || has2;
            if (!valid) continue;
            const int rloc = u * 32 + g + 8 * rp;
            float4 e0v = mbox[g + 8 * rp];
            float4 e1v = mbox[32 + g + 8 * rp];
            float M = fmaxf(e0v.x, e1v.x);
            float S = e0v.y * __expf(e0v.x - M) + e1v.y * __expf(e1v.x - M);
            const float myf = __expf(((p == 0) ? e0v.x : e1v.x) - M) / S;
            float* orow = out + ((size_t)it0 * TSTEPS + rloc) * CLS + 40 * p;
            #pragma unroll
            for (int j = 0; j < 5; j++) {
                int col = 40 * p + 8 * j + 2 * t;
                if (col < CLS)
                    *(float2*)(orow + 8 * j + 2 * t) =
                        make_float2(c[rt][j][2 * h] * myf, c[rt][j][2 * h + 1] * myf);
            }
            if (p == 0 && t == 0) {
                int best = (e1v.x > e0v.x) ? __float_as_int(e1v.z) : __float_as_int(e0v.z);
                sbest[rloc] = best;
            }
        }
    }

    // ---- all units done -> in-CTA CTC greedy decode ----
    __syncthreads();
    if (warp < nitems) {
        const int* bp = sbest + warp * TSTEPS;
        int v0 = bp[lane];
        int v1 = bp[lane + 32];
        int v2 = (lane < 16) ? bp[lane + 64] : BLANK;

        int p0 = __shfl_up_sync(full, v0, 1); if (lane == 0) p0 = -1;
        int t0 = __shfl_sync(full, v0, 31);
        int p1 = __shfl_up_sync(full, v1, 1); if (lane == 0) p1 = t0;
        int t1 = __shfl_sync(full, v1, 31);
        int p2 = __shfl_up_sync(full, v2, 1); if (lane == 0) p2 = t1;

        bool k0 = (v0 != BLANK) && (v0 != p0);
        bool k1 = (v1 != BLANK) && (v1 != p1);
        bool k2 = (lane < 16) && (v2 != BLANK) && (v2 != p2);
        unsigned m0 = __ballot_sync(full, k0);
        unsigned m1 = __ballot_sync(full, k1);
        unsigned m2 = __ballot_sync(full, k2);
        int c0 = __popc(m0), c1 = __popc(m1);
        unsigned lt = (1u << lane) - 1u;

        float* ob = out + (size_t)ROWS * CLS + (size_t)(it0 + warp) * PRED_LEN;
        if (lane < PRED_LEN) ob[lane] = -1.0f;
        __syncwarp();
        if (k0) { int q = __popc(m0 & lt);           if (q < PRED_LEN) ob[q] = (float)v0; }
        if (k1) { int q = c0 + __popc(m1 & lt);      if (q < PRED_LEN) ob[q] = (float)v1; }
        if (k2) { int q = c0 + c1 + __popc(m2 & lt); if (q < PRED_LEN) ob[q] = (float)v2; }
    }
}

// ---------------------------------------------------------------------------
extern "C" void kernel_launch(void* const* d_in, const int* in_sizes, int n_in,
                              void* d_out, int out_size)
{
    const float* feat = (const float*)d_in[0];
    const float* W    = (const float*)d_in[1];
    const float* b    = (const float*)d_in[2];
    float* out        = (float*)d_out;

    cudaFuncSetAttribute(ctc_fused_kernel,
                         cudaFuncAttributeMaxDynamicSharedMemorySize, SM_TOTAL);
    ctc_fused_kernel<<<NCTAS, THREADS, SM_TOTAL>>>(feat, W, b, out);
}

// round 11
// speedup vs baseline: 1.1276x; 1.1276x over previous
#include <cuda_runtime.h>
#include <cuda_bf16.h>
#include <cstdint>
#include <math.h>

// ---------------- problem constants ----------------
#define BATCH    1024
#define TSTEPS   80
#define DIM      512
#define CLS      78
#define BLANK    77
#define PRED_LEN 30
#define ROWS     (BATCH * TSTEPS)     // 81920

#define ITEMS_PER_CTA 7
#define NCTAS    147                  // 146*7 + 2 = 1024 items
#define THREADS  384                  // 12 warps
#define NKC      16                   // k32 chunks (512/32)
#define STAGE_B  2048                 // 16 rows x 32 fp32 per warp-stage

// ---------------- smem layout (bytes) ----------------
#define B_STRIDE  1088                // 1024 data + 64 pad (conflict-free LDS.128)
#define B_BYTES   (80 * B_STRIDE)     // 87040 each (hi, lo)
#define SM_BHI    0
#define SM_BLO    B_BYTES
#define SM_BIAS   (2 * B_BYTES)       // 174080 : 80 floats
#define SM_SBEST  (SM_BIAS + 320)     // 174400 : int sbest[560]
#define SM_CTR    (SM_SBEST + 2240)   // 176640
#define SM_A      176768              // 12 warps x 2 stages x 2KB = 49152
#define SM_TOTAL  (SM_A + 12 * 2 * STAGE_B)   // 225920

// B k-permutation matched to A fragments held as 4-consecutive-k float4s:
__device__ __forceinline__ int kperm(int k) {
    int grp = k >> 5, r = k & 31;
    int s = r >> 4;
    int t = (r & 15) >> 2;
    int idx = r & 3;
    return grp * 32 + t * 8 + s * 4 + idx;
}

__device__ __forceinline__ uint32_t pack_bf16(float a, float b) {
    uint32_t r;
    asm("cvt.rn.satfinite.bf16x2.f32 %0, %1, %2;" : "=r"(r) : "f"(b), "f"(a));
    return r;
}

__device__ __forceinline__ void split2(float a, float b, uint32_t& h, uint32_t& l) {
    h = pack_bf16(a, b);
    float ha = __uint_as_float(h << 16);
    float hb = __uint_as_float(h & 0xffff0000u);
    l = pack_bf16(a - ha, b - hb);
}

__device__ __forceinline__ void mma16816(float* c, uint32_t a0, uint32_t a1,
                                         uint32_t a2, uint32_t a3,
                                         uint32_t b0, uint32_t b1) {
    asm volatile(
        "mma.sync.aligned.m16n8k16.row.col.f32.bf16.bf16.f32 "
        "{%0,%1,%2,%3}, {%4,%5,%6,%7}, {%8,%9}, {%0,%1,%2,%3};"
        : "+f"(c[0]), "+f"(c[1]), "+f"(c[2]), "+f"(c[3])
        : "r"(a0), "r"(a1), "r"(a2), "r"(a3), "r"(b0), "r"(b1));
}

__device__ __forceinline__ void cp_async16(uint32_t dst_smem, const void* src) {
    asm volatile("cp.async.cg.shared.global [%0], [%1], 16;" :: "r"(dst_smem), "l"(src));
}

// warp-private: load 16 rows x k32 fp32 (2KB) into stage buf, slot-swizzled
__device__ __forceinline__ void issue_stage(const float* __restrict__ feat,
                                            size_t rb, int kc, uint32_t buf, int lane) {
    #pragma unroll
    for (int i = 0; i < 4; i++) {
        int slot = lane + 32 * i;        // 128 slots of 16B
        int row = slot >> 3, q = slot & 7;
        const float* src = feat + (rb + row) * DIM + kc * 32 + q * 4;
        cp_async16(buf + row * 128 + ((q ^ ((row & 1) << 2)) << 4), src);
    }
}

// ---------------------------------------------------------------------------
// Single kernel: GEMM (bf16-split HMMA, cp.async A) + softmax/argmax + decode
// ---------------------------------------------------------------------------
__global__ void __launch_bounds__(THREADS, 1)
ctc_fused_kernel(const float* __restrict__ feat,
                 const float* __restrict__ Wg,
                 const float* __restrict__ bg,
                 float* __restrict__ out)
{
    extern __shared__ char sm[];
    const int tid  = threadIdx.x;
    const int lane = tid & 31;
    const int warp = tid >> 5;
    const int g    = lane >> 2;
    const int t    = lane & 3;
    const unsigned full = 0xffffffffu;

    const int it0      = blockIdx.x * ITEMS_PER_CTA;
    const int nitems   = min(ITEMS_PER_CTA, BATCH - it0);
    const int nstrips  = nitems * (TSTEPS / 16);        // 16-row strips
    int* const sctr    = (int*)(sm + SM_CTR);
    int* const sbest   = (int*)(sm + SM_SBEST);

    if (tid == 0) *sctr = 0;

    // ---- build B = W^T bf16 hi/lo, k-permuted, zero-padded to 80 cols ----
    for (int idx = tid; idx < 80 * DIM; idx += THREADS) {
        int k = idx / 80;
        int n = idx - k * 80;
        float v = (n < CLS) ? Wg[k * CLS + n] : 0.0f;
        __nv_bfloat16 h = __float2bfloat16_rn(v);
        __nv_bfloat16 l = __float2bfloat16_rn(v - __bfloat162float(h));
        int byte = n * B_STRIDE + kperm(k) * 2;
        *(uint16_t*)(sm + SM_BHI + byte) = __bfloat16_as_ushort(h);
        *(uint16_t*)(sm + SM_BLO + byte) = __bfloat16_as_ushort(l);
    }
    if (tid < 80) ((float*)(sm + SM_BIAS))[tid] = (tid < CLS) ? bg[tid] : 0.0f;
    __syncthreads();
    const float* bias_sm = (const float*)(sm + SM_BIAS);

    const uint32_t myA =
        (uint32_t)__cvta_generic_to_shared(sm + SM_A) + warp * (2 * STAGE_B);

    for (;;) {
        int ls = 0;
        if (lane == 0) ls = atomicAdd(sctr, 1);
        ls = __shfl_sync(full, ls, 0);
        if (ls >= nstrips) break;
        const size_t rb = (size_t)it0 * TSTEPS + (size_t)ls * 16;

        float c[10][4];
        #pragma unroll
        for (int j = 0; j < 10; j++)
            { c[j][0] = 0.f; c[j][1] = 0.f; c[j][2] = 0.f; c[j][3] = 0.f; }

        // prologue: 2 stages in flight
        issue_stage(feat, rb, 0, myA, lane);
        asm volatile("cp.async.commit_group;" ::: "memory");
        issue_stage(feat, rb, 1, myA + STAGE_B, lane);
        asm volatile("cp.async.commit_group;" ::: "memory");

        #pragma unroll 2
        for (int kc = 0; kc < NKC; kc++) {
            if (kc + 1 < NKC)
                asm volatile("cp.async.wait_group 1;" ::: "memory");
            else
                asm volatile("cp.async.wait_group 0;" ::: "memory");

            // LDS this chunk's fp32 (swizzled, conflict-free)
            const uint32_t A = myA + (kc & 1) * STAGE_B;
            float4 F[2][2];              // [row-half rr][k16 step s]
            #pragma unroll
            for (int s = 0; s < 2; s++) {
                int q0 = ((4 * s + t) ^ ((g & 1) << 2)) << 4;
                asm volatile("ld.shared.v4.f32 {%0,%1,%2,%3}, [%4];"
                    : "=f"(F[0][s].x), "=f"(F[0][s].y), "=f"(F[0][s].z), "=f"(F[0][s].w)
                    : "r"(A + g * 128 + q0));
                asm volatile("ld.shared.v4.f32 {%0,%1,%2,%3}, [%4];"
                    : "=f"(F[1][s].x), "=f"(F[1][s].y), "=f"(F[1][s].z), "=f"(F[1][s].w)
                    : "r"(A + (g + 8) * 128 + q0));
            }

            uint32_t AH[2][2][2], AL[2][2][2];   // [rr][s][half]
            #pragma unroll
            for (int rr = 0; rr < 2; rr++)
                #pragma unroll
                for (int s = 0; s < 2; s++) {
                    split2(F[rr][s].x, F[rr][s].y, AH[rr][s][0], AL[rr][s][0]);
                    split2(F[rr][s].z, F[rr][s].w, AH[rr][s][1], AL[rr][s][1]);
                }

            // refill this slot for chunk kc+2 (F already consumed by split2)
            if (kc + 2 < NKC) {
                issue_stage(feat, rb, kc + 2, A, lane);
                asm volatile("cp.async.commit_group;" ::: "memory");
            }

            const int boff = kc * 64 + t * 16;
            #pragma unroll
            for (int jp = 0; jp < 5; jp++) {
                const int n0 = 16 * jp + g;
                const int n1 = n0 + 8;
                uint4 bh0 = *(const uint4*)(sm + SM_BHI + n0 * B_STRIDE + boff);
                uint4 bl0 = *(const uint4*)(sm + SM_BLO + n0 * B_STRIDE + boff);
                uint4 bh1 = *(const uint4*)(sm + SM_BHI + n1 * B_STRIDE + boff);
                uint4 bl1 = *(const uint4*)(sm + SM_BLO + n1 * B_STRIDE + boff);
                float* c0 = c[2 * jp];
                float* c1 = c[2 * jp + 1];
                mma16816(c0, AH[0][0][0], AH[1][0][0], AH[0][0][1], AH[1][0][1], bh0.x, bh0.y);
                mma16816(c1, AH[0][0][0], AH[1][0][0], AH[0][0][1], AH[1][0][1], bh1.x, bh1.y);
                mma16816(c0, AH[0][1][0], AH[1][1][0], AH[0][1][1], AH[1][1][1], bh0.z, bh0.w);
                mma16816(c1, AH[0][1][0], AH[1][1][0], AH[0][1][1], AH[1][1][1], bh1.z, bh1.w);
                mma16816(c0, AH[0][0][0], AH[1][0][0], AH[0][0][1], AH[1][0][1], bl0.x, bl0.y);
                mma16816(c1, AH[0][0][0], AH[1][0][0], AH[0][0][1], AH[1][0][1], bl1.x, bl1.y);
                mma16816(c0, AH[0][1][0], AH[1][1][0], AH[0][1][1], AH[1][1][1], bl0.z, bl0.w);
                mma16816(c1, AH[0][1][0], AH[1][1][0], AH[0][1][1], AH[1][1][1], bl1.z, bl1.w);
                mma16816(c0, AL[0][0][0], AL[1][0][0], AL[0][0][1], AL[1][0][1], bh0.x, bh0.y);
                mma16816(c1, AL[0][0][0], AL[1][0][0], AL[0][0][1], AL[1][0][1], bh1.x, bh1.y);
                mma16816(c0, AL[0][1][0], AL[1][1][0], AL[0][1][1], AL[1][1][1], bh0.z, bh0.w);
                mma16816(c1, AL[0][1][0], AL[1][1][0], AL[0][1][1], AL[1][1][1], bh1.z, bh1.w);
            }
        }

        // ---- epilogue: bias + softmax + argmax; rows rb+g and rb+g+8 ----
        float bb[10][2];
        #pragma unroll
        for (int j = 0; j < 10; j++) {
            float2 bv = *(const float2*)(bias_sm + 8 * j + 2 * t);
            bb[j][0] = bv.x; bb[j][1] = bv.y;
        }
        const size_t row0 = rb + g;
        const size_t row1 = rb + g + 8;
        float m0 = -INFINITY, m1 = -INFINITY;
        int i0 = 0, i1 = 0;
        #pragma unroll
        for (int j = 0; j < 10; j++) {
            #pragma unroll
            for (int h = 0; h < 2; h++) {
                int col = 8 * j + 2 * t + h;
                if (col < CLS) {
                    float v0 = c[j][h]     + bb[j][h];
                    float v1 = c[j][2 + h] + bb[j][h];
                    c[j][h]     = v0;
                    c[j][2 + h] = v1;
                    if (v0 > m0) { m0 = v0; i0 = col; }
                    if (v1 > m1) { m1 = v1; i1 = col; }
                }
            }
        }
        #pragma unroll
        for (int d = 1; d <= 2; d <<= 1) {
            float om0 = __shfl_xor_sync(full, m0, d);
            int   oi0 = __shfl_xor_sync(full, i0, d);
            if (om0 > m0 || (om0 == m0 && oi0 < i0)) { m0 = om0; i0 = oi0; }
            float om1 = __shfl_xor_sync(full, m1, d);
            int   oi1 = __shfl_xor_sync(full, i1, d);
            if (om1 > m1 || (om1 == m1 && oi1 < i1)) { m1 = om1; i1 = oi1; }
        }
        float s0 = 0.f, s1 = 0.f;
        #pragma unroll
        for (int j = 0; j < 10; j++) {
            #pragma unroll
            for (int h = 0; h < 2; h++) {
                int col = 8 * j + 2 * t + h;
                float e0 = 0.f, e1 = 0.f;
                if (col < CLS) {
                    e0 = __expf(c[j][h] - m0);
                    e1 = __expf(c[j][2 + h] - m1);
                }
                c[j][h] = e0; c[j][2 + h] = e1;
                s0 += e0; s1 += e1;
            }
        }
        #pragma unroll
        for (int d = 1; d <= 2; d <<= 1) {
            s0 += __shfl_xor_sync(full, s0, d);
            s1 += __shfl_xor_sync(full, s1, d);
        }
        const float v0inv = 1.0f / s0;
        const float v1inv = 1.0f / s1;
        #pragma unroll
        for (int j = 0; j < 10; j++) {
            int col = 8 * j + 2 * t;
            if (col < CLS) {  // skips only col 78 (j=9,t=3)
                *(float2*)(out + row0 * CLS + col) =
                    make_float2(c[j][0] * v0inv, c[j][1] * v0inv);
                *(float2*)(out + row1 * CLS + col) =
                    make_float2(c[j][2] * v1inv, c[j][3] * v1inv);
            }
        }
        if (t == 0) {
            sbest[ls * 16 + g]     = i0;
            sbest[ls * 16 + g + 8] = i1;
        }
    }

    // ---- all strips done -> in-CTA CTC greedy decode ----
    __syncthreads();
    if (warp < nitems) {
        const int* bp = sbest + warp * TSTEPS;
        int v0 = bp[lane];
        int v1 = bp[lane + 32];
        int v2 = (lane < 16) ? bp[lane + 64] : BLANK;

        int p0 = __shfl_up_sync(full, v0, 1); if (lane == 0) p0 = -1;
        int t0 = __shfl_sync(full, v0, 31);
        int p1 = __shfl_up_sync(full, v1, 1); if (lane == 0) p1 = t0;
        int t1 = __shfl_sync(full, v1, 31);
        int p2 = __shfl_up_sync(full, v2, 1); if (lane == 0) p2 = t1;

        bool k0 = (v0 != BLANK) && (v0 != p0);
        bool k1 = (v1 != BLANK) && (v1 != p1);
        bool k2 = (lane < 16) && (v2 != BLANK) && (v2 != p2);
        unsigned m0 = __ballot_sync(full, k0);
        unsigned m1 = __ballot_sync(full, k1);
        unsigned m2 = __ballot_sync(full, k2);
        int c0 = __popc(m0), c1 = __popc(m1);
        unsigned lt = (1u << lane) - 1u;

        float* ob = out + (size_t)ROWS * CLS + (size_t)(it0 + warp) * PRED_LEN;
        if (lane < PRED_LEN) ob[lane] = -1.0f;
        __syncwarp();
        if (k0) { int q = __popc(m0 & lt);           if (q < PRED_LEN) ob[q] = (float)v0; }
        if (k1) { int q = c0 + __popc(m1 & lt);      if (q < PRED_LEN) ob[q] = (float)v1; }
        if (k2) { int q = c0 + c1 + __popc(m2 & lt); if (q < PRED_LEN) ob[q] = (float)v2; }
    }
}

// ---------------------------------------------------------------------------
extern "C" void kernel_launch(void* const* d_in, const int* in_sizes, int n_in,
                              void* d_out, int out_size)
{
    const float* feat = (const float*)d_in[0];
    const float* W    = (const float*)d_in[1];
    const float* b    = (const float*)d_in[2];
    float* out        = (float*)d_out;

    cudaFuncSetAttribute(ctc_fused_kernel,
                         cudaFuncAttributeMaxDynamicSharedMemorySize, SM_TOTAL);
    ctc_fused_kernel<<<NCTAS, THREADS, SM_TOTAL>>>(feat, W, b, out);
}